// round 15
// baseline (speedup 1.0000x reference)
#include <cuda_runtime.h>
#include <cuda_fp16.h>
#include <math.h>
#include <stdint.h>
#include <string.h>

#define NROWS 8192
#define H 512
#define CC 100
#define RR 69
#define PP 69
#define EPSV 1e-8f

typedef unsigned long long ull;

// ---------------- scratch (device globals, no runtime alloc) ----------------
__device__ __half g_vcat[(size_t)NROWS * 3 * H];
__device__ __half g_h[(size_t)NROWS * H];
__device__ float  g_vf[(size_t)NROWS * H];
__device__ __half g_rf[(size_t)NROWS * 2 * H];
__device__ __half g_h2[(size_t)NROWS * H];          // fp16 now (feeds tensor GEMM6)
__device__ __half g_w1t[(size_t)H * 3 * H];
__device__ __half g_w2t[(size_t)H * H];
__device__ __half g_rw1t[(size_t)H * 2 * H];
__device__ __half g_rw2t[(size_t)128 * H];          // padded to 128 rows, zero-filled
__device__ float  g_rb2p[128];                      // padded bias, zero-filled

// ---------------- helpers ----------------
__device__ __forceinline__ uint32_t pack_h2(float a, float b) {
    __half2 h = __floats2half2_rn(a, b);
    uint32_t r; memcpy(&r, &h, 4); return r;
}
__device__ __forceinline__ uint32_t smem_u32(const void* p) {
    return (uint32_t)__cvta_generic_to_shared(p);
}
__device__ __forceinline__ void cp_async16(uint32_t smem_dst, const void* gmem_src) {
    asm volatile("cp.async.cg.shared.global [%0], [%1], 16;" :: "r"(smem_dst), "l"(gmem_src) : "memory");
}
__device__ __forceinline__ void cp_commit() {
    asm volatile("cp.async.commit_group;" ::: "memory");
}
#define CP_WAIT(n) asm volatile("cp.async.wait_group %0;" :: "n"(n) : "memory")

__device__ __forceinline__ void mma16816(float* d, const uint32_t* a, const uint32_t* b) {
    asm volatile(
        "mma.sync.aligned.m16n8k16.row.col.f32.f16.f16.f32 "
        "{%0,%1,%2,%3},{%4,%5,%6,%7},{%8,%9},{%0,%1,%2,%3};"
        : "+f"(d[0]), "+f"(d[1]), "+f"(d[2]), "+f"(d[3])
        : "r"(a[0]), "r"(a[1]), "r"(a[2]), "r"(a[3]), "r"(b[0]), "r"(b[1]));
}
__device__ __forceinline__ void ldsm4(uint32_t& r0, uint32_t& r1, uint32_t& r2, uint32_t& r3,
                                      uint32_t addr) {
    asm volatile("ldmatrix.sync.aligned.m8n8.x4.shared.b16 {%0,%1,%2,%3}, [%4];"
        : "=r"(r0), "=r"(r1), "=r"(r2), "=r"(r3) : "r"(addr));
}

// ---------------- concat -> fp16 ----------------
__global__ void concat_kernel(const float* __restrict__ s,
                              const float* __restrict__ p,
                              const float* __restrict__ o) {
    size_t idx = (size_t)blockIdx.x * blockDim.x + threadIdx.x;   // float4 index
    size_t total = (size_t)NROWS * 3 * H / 4;
    if (idx >= total) return;
    size_t row = idx / (3 * H / 4);
    size_t col4 = idx % (3 * H / 4);
    const float4* src;
    size_t within;
    if (col4 < H / 4)            { src = (const float4*)s; within = col4; }
    else if (col4 < 2 * (H / 4)) { src = (const float4*)p; within = col4 - H / 4; }
    else                         { src = (const float4*)o; within = col4 - 2 * (H / 4); }
    float4 v = src[row * (H / 4) + within];
    uint32_t* d = (uint32_t*)(g_vcat + idx * 4);
    d[0] = pack_h2(v.x, v.y);
    d[1] = pack_h2(v.z, v.w);
}

// ---------------- weight transpose: W[K,N] f32 -> T[N,K] fp16 ----------------
__global__ void wtrans_kernel(const float* __restrict__ W,
                              __half* __restrict__ T,
                              int K, int N) {
    size_t idx = (size_t)blockIdx.x * blockDim.x + threadIdx.x;
    size_t total = (size_t)K * N;
    if (idx >= total) return;
    int n = (int)(idx / K);
    int k = (int)(idx % K);
    T[idx] = __float2half_rn(W[(size_t)k * N + n]);
}

// ---------------- bias pad copy ----------------
__global__ void biaspad_kernel(const float* __restrict__ b) {
    int i = threadIdx.x;
    g_rb2p[i] = (i < PP) ? b[i] : 0.f;
}

// ---------------- fp16 single-pass mma.sync GEMM ----------------
#define TG_LDS 72
#define TG_STAGES 3
#define TG_STAGE_ELEMS (128 * TG_LDS)
#define TG_SMEM (2 * TG_STAGES * TG_STAGE_ELEMS * 2)
#define TG_ROWB (TG_LDS * 2)

template<bool WH16, bool WF32, bool RELU>
__global__ __launch_bounds__(256, 2)
void tgemm_kernel(const __half* __restrict__ A, const __half* __restrict__ B,
                  const float* __restrict__ bias,
                  __half* __restrict__ Ch, float* __restrict__ Cf32,
                  int K, int Ntot) {
    extern __shared__ __align__(16) __half smem[];

    const int tid = threadIdx.x;
    const int wid = tid >> 5;
    const int lane = tid & 31;
    const int g = lane >> 2;
    const int t = lane & 3;
    const int wm = wid & 3;
    const int wn = wid >> 2;
    const int bm = blockIdx.y * 128;
    const int bn = blockIdx.x * 128;

    const int C = K >> 6;

    const uint32_t aoff = (uint32_t)((wm * 32 + (lane & 15)) * TG_ROWB + ((lane >> 4) * 8) * 2);
    const uint32_t boff = (uint32_t)((wn * 64 + ((lane >> 3) >> 1) * 8 + (lane & 7)) * TG_ROWB
                                     + (((lane >> 3) & 1) * 8) * 2);

    float acc[2][8][4];
#pragma unroll
    for (int i = 0; i < 2; i++)
#pragma unroll
        for (int j = 0; j < 8; j++)
#pragma unroll
            for (int q = 0; q < 4; q++) acc[i][j][q] = 0.f;

    auto load_chunk = [&](int c, int s) {
        int kc = c << 6;
        uint32_t abase = smem_u32(smem + s * TG_STAGE_ELEMS);
        uint32_t bbase = smem_u32(smem + (TG_STAGES + s) * TG_STAGE_ELEMS);
#pragma unroll
        for (int i = 0; i < 4; i++) {
            int seg = tid + i * 256;
            int row = seg >> 3, sg = seg & 7;
            cp_async16(abase + (row * TG_LDS + sg * 8) * 2,
                       A + (size_t)(bm + row) * K + kc + sg * 8);
        }
#pragma unroll
        for (int i = 0; i < 4; i++) {
            int seg = tid + i * 256;
            int row = seg >> 3, sg = seg & 7;
            cp_async16(bbase + (row * TG_LDS + sg * 8) * 2,
                       B + (size_t)(bn + row) * K + kc + sg * 8);
        }
        cp_commit();
    };

    load_chunk(0, 0);
    load_chunk(1, 1);
    load_chunk(2, 2);

    for (int c = 0; c < C; c++) {
        const int s = c % TG_STAGES;
        CP_WAIT(2);
        __syncthreads();

        const uint32_t abase = smem_u32(smem + s * TG_STAGE_ELEMS) + aoff;
        const uint32_t bbase = smem_u32(smem + (TG_STAGES + s) * TG_STAGE_ELEMS) + boff;

        uint32_t af[2][2][4];
        uint32_t bf[2][4][4];

        ldsm4(af[0][0][0], af[0][0][1], af[0][0][2], af[0][0][3], abase);
        ldsm4(af[0][1][0], af[0][1][1], af[0][1][2], af[0][1][3], abase + 16 * TG_ROWB);
#pragma unroll
        for (int ntp = 0; ntp < 4; ntp++)
            ldsm4(bf[0][ntp][0], bf[0][ntp][1], bf[0][ntp][2], bf[0][ntp][3],
                  bbase + ntp * 16 * TG_ROWB);

#pragma unroll
        for (int ks = 0; ks < 4; ks++) {
            const int cur = ks & 1;
            const int nxt = cur ^ 1;
            if (ks < 3) {
                const uint32_t k2 = (ks + 1) * 32;
                ldsm4(af[nxt][0][0], af[nxt][0][1], af[nxt][0][2], af[nxt][0][3], abase + k2);
                ldsm4(af[nxt][1][0], af[nxt][1][1], af[nxt][1][2], af[nxt][1][3],
                      abase + 16 * TG_ROWB + k2);
#pragma unroll
                for (int ntp = 0; ntp < 4; ntp++)
                    ldsm4(bf[nxt][ntp][0], bf[nxt][ntp][1], bf[nxt][ntp][2], bf[nxt][ntp][3],
                          bbase + ntp * 16 * TG_ROWB + k2);
            }
#pragma unroll
            for (int ntp = 0; ntp < 4; ntp++) {
                mma16816(acc[0][2 * ntp],     af[cur][0], bf[cur][ntp]);
                mma16816(acc[1][2 * ntp],     af[cur][1], bf[cur][ntp]);
                mma16816(acc[0][2 * ntp + 1], af[cur][0], bf[cur][ntp] + 2);
                mma16816(acc[1][2 * ntp + 1], af[cur][1], bf[cur][ntp] + 2);
            }
        }
        __syncthreads();
        if (c + 3 < C) load_chunk(c + 3, s);
        else cp_commit();
    }

    // epilogue (WF32 path handles partial / odd-width tiles safely)
    const bool fullvec = ((Ntot & 1) == 0);
#pragma unroll
    for (int mt = 0; mt < 2; mt++) {
        int row0 = bm + wm * 32 + mt * 16 + g;
        int row1 = row0 + 8;
#pragma unroll
        for (int nt = 0; nt < 8; nt++) {
            int col = bn + wn * 64 + nt * 8 + 2 * t;
            float2 bv = __ldg((const float2*)(bias + col));
            float v0 = acc[mt][nt][0] + bv.x;
            float v1 = acc[mt][nt][1] + bv.y;
            float v2 = acc[mt][nt][2] + bv.x;
            float v3 = acc[mt][nt][3] + bv.y;
            if (RELU) {
                v0 = fmaxf(v0, 0.f); v1 = fmaxf(v1, 0.f);
                v2 = fmaxf(v2, 0.f); v3 = fmaxf(v3, 0.f);
            }
            if (WF32) {
                if (fullvec && col + 2 <= Ntot) {
                    *(float2*)(Cf32 + (size_t)row0 * Ntot + col) = make_float2(v0, v1);
                    *(float2*)(Cf32 + (size_t)row1 * Ntot + col) = make_float2(v2, v3);
                } else {
                    if (col < Ntot) {
                        Cf32[(size_t)row0 * Ntot + col] = v0;
                        Cf32[(size_t)row1 * Ntot + col] = v2;
                    }
                    if (col + 1 < Ntot) {
                        Cf32[(size_t)row0 * Ntot + col + 1] = v1;
                        Cf32[(size_t)row1 * Ntot + col + 1] = v3;
                    }
                }
            }
            if (WH16) {
                *(uint32_t*)(Ch + (size_t)row0 * Ntot + col) = pack_h2(v0, v1);
                *(uint32_t*)(Ch + (size_t)row1 * Ntot + col) = pack_h2(v2, v3);
            }
        }
    }
}

// ---------------- streaming online-softmax attention (R12 WIN, unchanged) ----------------
#define ACH 8
#define ASTAGES 3
#define A_SMEM ((ASTAGES * ACH * H + H + 4 * ACH + 8) * 4)

__global__ __launch_bounds__(256)
void attn_kernel(const float* __restrict__ vf,
                 const float* __restrict__ rel_base,
                 const int* __restrict__ scats,
                 const int* __restrict__ ocats,
                 __half* __restrict__ rf) {
    extern __shared__ float sm[];
    float* ring  = sm;
    float* svf   = ring + ASTAGES * ACH * H;
    float* sdot  = svf + H;
    float* ssq   = sdot + ACH;
    float* sw    = ssq + ACH;
    float* sred  = sw + ACH;
    float* sstat = sred + 8;

    const int n = blockIdx.x;
    const int tid = threadIdx.x;
    const int lane = tid & 31;
    const int warp = tid >> 5;

    const int s = scats[n];
    const int o = ocats[n];
    const float* relp = rel_base + (((size_t)s * RR) * CC + o) * H;

    auto load_chunk = [&](int tc) {
        float* dst = ring + (tc % ASTAGES) * (ACH * H);
#pragma unroll
        for (int i = 0; i < 4; i++) {
            int idx = tid + i * 256;
            int j = idx >> 7;
            int col4 = idx & 127;
            int r = tc * ACH + j;
            if (r < RR)
                cp_async16(smem_u32(dst + j * H + col4 * 4),
                           relp + (size_t)r * CC * H + col4 * 4);
        }
        cp_commit();
    };

    if (tid < 128)
        ((float4*)svf)[tid] = __ldg(&((const float4*)(vf + (size_t)n * H))[tid]);

    load_chunk(0);
    load_chunk(1);
    load_chunk(2);

    __syncthreads();
    {
        float v0 = svf[tid], v1 = svf[tid + 256];
        float part = v0 * v0 + v1 * v1;
#pragma unroll
        for (int off = 16; off > 0; off >>= 1)
            part += __shfl_xor_sync(0xffffffffu, part, off);
        if (lane == 0) sred[warp] = part;
    }

    const int chunks = (RR + ACH - 1) / ACH;
    float acc0 = 0.f, acc1 = 0.f;
    float m_run = -1e30f, s_run = 0.f, vn = 0.f;

    for (int tc = 0; tc < chunks; tc++) {
        CP_WAIT(2);
        __syncthreads();

        {
            const float4* cb4 = (const float4*)(ring + (tc % ASTAGES) * (ACH * H) + warp * H);
            const float4* vf4s = (const float4*)svf;
            float dot = 0.f, sq = 0.f;
#pragma unroll
            for (int i = 0; i < 4; i++) {
                float4 x = cb4[lane + 32 * i];
                float4 v = vf4s[lane + 32 * i];
                dot += x.x * v.x + x.y * v.y + x.z * v.z + x.w * v.w;
                sq  += x.x * x.x + x.y * x.y + x.z * x.z + x.w * x.w;
            }
#pragma unroll
            for (int off = 16; off > 0; off >>= 1) {
                dot += __shfl_down_sync(0xffffffffu, dot, off);
                sq  += __shfl_down_sync(0xffffffffu, sq, off);
            }
            if (lane == 0) { sdot[warp] = dot; ssq[warp] = sq; }
        }
        __syncthreads();

        if (warp == 0) {
            if (tc == 0) {
                float vsq = (lane < 8) ? sred[lane] : 0.f;
#pragma unroll
                for (int off = 4; off > 0; off >>= 1)
                    vsq += __shfl_xor_sync(0xffffffffu, vsq, off);
                vsq = __shfl_sync(0xffffffffu, vsq, 0);
                vn = sqrtf(vsq);
            }
            int r = tc * ACH + lane;
            float c = -1e30f;
            if (lane < ACH && r < RR)
                c = sdot[lane] / fmaxf(vn * sqrtf(ssq[lane]), EPSV);
            float mc = c;
#pragma unroll
            for (int off = 16; off > 0; off >>= 1)
                mc = fmaxf(mc, __shfl_xor_sync(0xffffffffu, mc, off));
            float m_new = fmaxf(m_run, mc);
            float w = (lane < ACH) ? __expf(c - m_new) : 0.f;
            float wsum = w;
#pragma unroll
            for (int off = 16; off > 0; off >>= 1)
                wsum += __shfl_xor_sync(0xffffffffu, wsum, off);
            float scale = __expf(m_run - m_new);
            s_run = s_run * scale + wsum;
            m_run = m_new;
            if (lane < ACH) sw[lane] = w;
            if (lane == 0) sstat[0] = scale;
            if (lane == 0 && tc == chunks - 1) sstat[1] = s_run;
        }
        __syncthreads();

        {
            float scale = sstat[0];
            acc0 *= scale; acc1 *= scale;
            const float* cb = ring + (tc % ASTAGES) * (ACH * H);
#pragma unroll
            for (int r = 0; r < ACH; r++) {
                float wr = sw[r];
                acc0 = fmaf(wr, cb[r * H + tid], acc0);
                acc1 = fmaf(wr, cb[r * H + tid + 256], acc1);
            }
        }
        __syncthreads();

        if (tc + 3 < chunks) load_chunk(tc + 3);
        else cp_commit();
    }

    float inv = 1.f / sstat[1];
    float att0 = acc0 * inv, att1 = acc1 * inv;
    float vv0 = svf[tid], vv1 = svf[tid + 256];

    size_t base = (size_t)n * 2 * H;
    rf[base + tid]           = __float2half_rn(vv0);
    rf[base + tid + 256]     = __float2half_rn(vv1);
    rf[base + H + tid]       = __float2half_rn(att0);
    rf[base + H + tid + 256] = __float2half_rn(att1);
}

// ---------------- launch ----------------
extern "C" void kernel_launch(void* const* d_in, const int* in_sizes, int n_in,
                              void* d_out, int out_size) {
    if (n_in < 14) return;
    const float* sfeat = (const float*)d_in[0];
    const float* pfeat = (const float*)d_in[1];
    const float* ofeat = (const float*)d_in[2];
    const float* rel   = (const float*)d_in[3];
    const float* w1    = (const float*)d_in[4];
    const float* b1    = (const float*)d_in[5];
    const float* w2    = (const float*)d_in[6];
    const float* b2    = (const float*)d_in[7];
    const float* rw1   = (const float*)d_in[8];
    const float* rb1   = (const float*)d_in[9];
    const float* rw2   = (const float*)d_in[10];
    const float* rb2   = (const float*)d_in[11];
    const int*   scats = (const int*)d_in[12];
    const int*   ocats = (const int*)d_in[13];
    float* out = (float*)d_out;

    __half *p_vcat, *p_h, *p_rf, *p_h2, *p_w1t, *p_w2t, *p_rw1t, *p_rw2t;
    float *p_vf;
    void *p_rw2t_v;
    cudaGetSymbolAddress((void**)&p_vcat, g_vcat);
    cudaGetSymbolAddress((void**)&p_h, g_h);
    cudaGetSymbolAddress((void**)&p_vf, g_vf);
    cudaGetSymbolAddress((void**)&p_rf, g_rf);
    cudaGetSymbolAddress((void**)&p_h2, g_h2);
    cudaGetSymbolAddress((void**)&p_w1t, g_w1t);
    cudaGetSymbolAddress((void**)&p_w2t, g_w2t);
    cudaGetSymbolAddress((void**)&p_rw1t, g_rw1t);
    cudaGetSymbolAddress((void**)&p_rw2t, g_rw2t);
    p_rw2t_v = (void*)p_rw2t;
    float* p_rb2p;
    cudaGetSymbolAddress((void**)&p_rb2p, g_rb2p);

    const int thr = 256;

    // 0) weight transpose -> fp16 (+ padded rw2t / bias)
    wtrans_kernel<<<(int)(((size_t)3 * H * H + thr - 1) / thr), thr>>>(w1, p_w1t, 3 * H, H);
    wtrans_kernel<<<(int)(((size_t)H * H + thr - 1) / thr), thr>>>(w2, p_w2t, H, H);
    wtrans_kernel<<<(int)(((size_t)2 * H * H + thr - 1) / thr), thr>>>(rw1, p_rw1t, 2 * H, H);
    cudaMemsetAsync(p_rw2t_v, 0, (size_t)128 * H * sizeof(__half));
    wtrans_kernel<<<(int)(((size_t)H * PP + thr - 1) / thr), thr>>>(rw2, p_rw2t, H, PP);
    biaspad_kernel<<<1, 128>>>(rb2);

    // 1) concat -> fp16
    {
        size_t total4 = (size_t)NROWS * 3 * H / 4;
        concat_kernel<<<(int)((total4 + thr - 1) / thr), thr>>>(sfeat, pfeat, ofeat);
    }
    // 2) h = relu(vcat @ w1 + b1) -> fp16
    {
        cudaFuncSetAttribute(tgemm_kernel<true, false, true>,
                             cudaFuncAttributeMaxDynamicSharedMemorySize, TG_SMEM);
        dim3 grid(H / 128, NROWS / 128);
        tgemm_kernel<true, false, true><<<grid, 256, TG_SMEM>>>(
            p_vcat, p_w1t, b1, p_h, nullptr, 3 * H, H);
    }
    // 3) vf = relu(h @ w2 + b2) -> f32
    {
        cudaFuncSetAttribute(tgemm_kernel<false, true, true>,
                             cudaFuncAttributeMaxDynamicSharedMemorySize, TG_SMEM);
        dim3 grid(H / 128, NROWS / 128);
        tgemm_kernel<false, true, true><<<grid, 256, TG_SMEM>>>(
            p_h, p_w2t, b2, nullptr, p_vf, H, H);
    }
    // 4) streaming attention -> rf fp16
    {
        cudaFuncSetAttribute(attn_kernel, cudaFuncAttributeMaxDynamicSharedMemorySize, A_SMEM);
        attn_kernel<<<NROWS, 256, A_SMEM>>>(p_vf, rel, scats, ocats, p_rf);
    }
    // 5) h2 = relu(rf @ rw1 + rb1) -> fp16
    {
        dim3 grid(H / 128, NROWS / 128);
        tgemm_kernel<true, false, true><<<grid, 256, TG_SMEM>>>(
            p_rf, p_rw1t, rb1, p_h2, nullptr, 2 * H, H);
    }
    // 6) plogits = h2 @ rw2 + rb2  (tensor path, padded N, guarded epilogue)
    {
        cudaFuncSetAttribute(tgemm_kernel<false, true, false>,
                             cudaFuncAttributeMaxDynamicSharedMemorySize, TG_SMEM);
        dim3 grid(1, NROWS / 128);
        tgemm_kernel<false, true, false><<<grid, 256, TG_SMEM>>>(
            p_h2, p_rw2t, p_rb2p, nullptr, out, H, PP);
    }
}

// round 16
// speedup vs baseline: 1.0071x; 1.0071x over previous
#include <cuda_runtime.h>
#include <cuda_fp16.h>
#include <math.h>
#include <stdint.h>
#include <string.h>

#define NROWS 8192
#define H 512
#define CC 100
#define RR 69
#define PP 69
#define EPSV 1e-8f

typedef unsigned long long ull;

// ---------------- scratch (device globals, no runtime alloc) ----------------
__device__ __half g_vcat[(size_t)NROWS * 3 * H];
__device__ __half g_h[(size_t)NROWS * H];
__device__ float  g_vf[(size_t)NROWS * H];
__device__ __half g_rf[(size_t)NROWS * 2 * H];
__device__ __half g_h2[(size_t)NROWS * H];          // fp16 (feeds tensor GEMM6)
__device__ __half g_w1t[(size_t)H * 3 * H];
__device__ __half g_w2t[(size_t)H * H];
__device__ __half g_rw1t[(size_t)H * 2 * H];
__device__ __half g_rw2t[(size_t)128 * H];          // padded to 128 rows, zero-filled
__device__ float  g_rb2p[128];                      // padded bias, zero-filled

// ---------------- helpers ----------------
__device__ __forceinline__ uint32_t pack_h2(float a, float b) {
    __half2 h = __floats2half2_rn(a, b);
    uint32_t r; memcpy(&r, &h, 4); return r;
}
__device__ __forceinline__ uint32_t smem_u32(const void* p) {
    return (uint32_t)__cvta_generic_to_shared(p);
}
__device__ __forceinline__ void cp_async16(uint32_t smem_dst, const void* gmem_src) {
    asm volatile("cp.async.cg.shared.global [%0], [%1], 16;" :: "r"(smem_dst), "l"(gmem_src) : "memory");
}
__device__ __forceinline__ void cp_commit() {
    asm volatile("cp.async.commit_group;" ::: "memory");
}
#define CP_WAIT(n) asm volatile("cp.async.wait_group %0;" :: "n"(n) : "memory")

__device__ __forceinline__ void mma16816(float* d, const uint32_t* a, const uint32_t* b) {
    asm volatile(
        "mma.sync.aligned.m16n8k16.row.col.f32.f16.f16.f32 "
        "{%0,%1,%2,%3},{%4,%5,%6,%7},{%8,%9},{%0,%1,%2,%3};"
        : "+f"(d[0]), "+f"(d[1]), "+f"(d[2]), "+f"(d[3])
        : "r"(a[0]), "r"(a[1]), "r"(a[2]), "r"(a[3]), "r"(b[0]), "r"(b[1]));
}
__device__ __forceinline__ void ldsm4(uint32_t& r0, uint32_t& r1, uint32_t& r2, uint32_t& r3,
                                      uint32_t addr) {
    asm volatile("ldmatrix.sync.aligned.m8n8.x4.shared.b16 {%0,%1,%2,%3}, [%4];"
        : "=r"(r0), "=r"(r1), "=r"(r2), "=r"(r3) : "r"(addr));
}

// ---------------- concat -> fp16 ----------------
__global__ void concat_kernel(const float* __restrict__ s,
                              const float* __restrict__ p,
                              const float* __restrict__ o) {
    size_t idx = (size_t)blockIdx.x * blockDim.x + threadIdx.x;   // float4 index
    size_t total = (size_t)NROWS * 3 * H / 4;
    if (idx >= total) return;
    size_t row = idx / (3 * H / 4);
    size_t col4 = idx % (3 * H / 4);
    const float4* src;
    size_t within;
    if (col4 < H / 4)            { src = (const float4*)s; within = col4; }
    else if (col4 < 2 * (H / 4)) { src = (const float4*)p; within = col4 - H / 4; }
    else                         { src = (const float4*)o; within = col4 - 2 * (H / 4); }
    float4 v = src[row * (H / 4) + within];
    uint32_t* d = (uint32_t*)(g_vcat + idx * 4);
    d[0] = pack_h2(v.x, v.y);
    d[1] = pack_h2(v.z, v.w);
}

// ---------------- weight transpose: W[K,N] f32 -> T[N,K] fp16 ----------------
__global__ void wtrans_kernel(const float* __restrict__ W,
                              __half* __restrict__ T,
                              int K, int N) {
    size_t idx = (size_t)blockIdx.x * blockDim.x + threadIdx.x;
    size_t total = (size_t)K * N;
    if (idx >= total) return;
    int n = (int)(idx / K);
    int k = (int)(idx % K);
    T[idx] = __float2half_rn(W[(size_t)k * N + n]);
}

// ---------------- bias pad copy ----------------
__global__ void biaspad_kernel(const float* __restrict__ b) {
    int i = threadIdx.x;
    g_rb2p[i] = (i < PP) ? b[i] : 0.f;
}

// ---------------- fp16 single-pass mma.sync GEMM ----------------
#define TG_LDS 72
#define TG_STAGES 3
#define TG_STAGE_ELEMS (128 * TG_LDS)
#define TG_SMEM (2 * TG_STAGES * TG_STAGE_ELEMS * 2)
#define TG_ROWB (TG_LDS * 2)

template<bool WH16, bool WF32, bool RELU>
__global__ __launch_bounds__(256, 2)
void tgemm_kernel(const __half* __restrict__ A, const __half* __restrict__ B,
                  const float* __restrict__ bias,
                  __half* __restrict__ Ch, float* __restrict__ Cf32,
                  int K, int Ntot) {
    extern __shared__ __align__(16) __half smem[];

    const int tid = threadIdx.x;
    const int wid = tid >> 5;
    const int lane = tid & 31;
    const int g = lane >> 2;
    const int t = lane & 3;
    const int wm = wid & 3;
    const int wn = wid >> 2;
    const int bm = blockIdx.y * 128;
    const int bn = blockIdx.x * 128;

    const int C = K >> 6;

    const uint32_t aoff = (uint32_t)((wm * 32 + (lane & 15)) * TG_ROWB + ((lane >> 4) * 8) * 2);
    const uint32_t boff = (uint32_t)((wn * 64 + ((lane >> 3) >> 1) * 8 + (lane & 7)) * TG_ROWB
                                     + (((lane >> 3) & 1) * 8) * 2);

    float acc[2][8][4];
#pragma unroll
    for (int i = 0; i < 2; i++)
#pragma unroll
        for (int j = 0; j < 8; j++)
#pragma unroll
            for (int q = 0; q < 4; q++) acc[i][j][q] = 0.f;

    auto load_chunk = [&](int c, int s) {
        int kc = c << 6;
        uint32_t abase = smem_u32(smem + s * TG_STAGE_ELEMS);
        uint32_t bbase = smem_u32(smem + (TG_STAGES + s) * TG_STAGE_ELEMS);
#pragma unroll
        for (int i = 0; i < 4; i++) {
            int seg = tid + i * 256;
            int row = seg >> 3, sg = seg & 7;
            cp_async16(abase + (row * TG_LDS + sg * 8) * 2,
                       A + (size_t)(bm + row) * K + kc + sg * 8);
        }
#pragma unroll
        for (int i = 0; i < 4; i++) {
            int seg = tid + i * 256;
            int row = seg >> 3, sg = seg & 7;
            cp_async16(bbase + (row * TG_LDS + sg * 8) * 2,
                       B + (size_t)(bn + row) * K + kc + sg * 8);
        }
        cp_commit();
    };

    load_chunk(0, 0);
    load_chunk(1, 1);
    load_chunk(2, 2);

    for (int c = 0; c < C; c++) {
        const int s = c % TG_STAGES;
        CP_WAIT(2);
        __syncthreads();

        const uint32_t abase = smem_u32(smem + s * TG_STAGE_ELEMS) + aoff;
        const uint32_t bbase = smem_u32(smem + (TG_STAGES + s) * TG_STAGE_ELEMS) + boff;

        uint32_t af[2][2][4];
        uint32_t bf[2][4][4];

        ldsm4(af[0][0][0], af[0][0][1], af[0][0][2], af[0][0][3], abase);
        ldsm4(af[0][1][0], af[0][1][1], af[0][1][2], af[0][1][3], abase + 16 * TG_ROWB);
#pragma unroll
        for (int ntp = 0; ntp < 4; ntp++)
            ldsm4(bf[0][ntp][0], bf[0][ntp][1], bf[0][ntp][2], bf[0][ntp][3],
                  bbase + ntp * 16 * TG_ROWB);

#pragma unroll
        for (int ks = 0; ks < 4; ks++) {
            const int cur = ks & 1;
            const int nxt = cur ^ 1;
            if (ks < 3) {
                const uint32_t k2 = (ks + 1) * 32;
                ldsm4(af[nxt][0][0], af[nxt][0][1], af[nxt][0][2], af[nxt][0][3], abase + k2);
                ldsm4(af[nxt][1][0], af[nxt][1][1], af[nxt][1][2], af[nxt][1][3],
                      abase + 16 * TG_ROWB + k2);
#pragma unroll
                for (int ntp = 0; ntp < 4; ntp++)
                    ldsm4(bf[nxt][ntp][0], bf[nxt][ntp][1], bf[nxt][ntp][2], bf[nxt][ntp][3],
                          bbase + ntp * 16 * TG_ROWB + k2);
            }
#pragma unroll
            for (int ntp = 0; ntp < 4; ntp++) {
                mma16816(acc[0][2 * ntp],     af[cur][0], bf[cur][ntp]);
                mma16816(acc[1][2 * ntp],     af[cur][1], bf[cur][ntp]);
                mma16816(acc[0][2 * ntp + 1], af[cur][0], bf[cur][ntp] + 2);
                mma16816(acc[1][2 * ntp + 1], af[cur][1], bf[cur][ntp] + 2);
            }
        }
        __syncthreads();
        if (c + 3 < C) load_chunk(c + 3, s);
        else cp_commit();
    }

    // epilogue (WF32 path handles partial / odd-width tiles safely)
    const bool fullvec = ((Ntot & 1) == 0);
#pragma unroll
    for (int mt = 0; mt < 2; mt++) {
        int row0 = bm + wm * 32 + mt * 16 + g;
        int row1 = row0 + 8;
#pragma unroll
        for (int nt = 0; nt < 8; nt++) {
            int col = bn + wn * 64 + nt * 8 + 2 * t;
            float2 bv = __ldg((const float2*)(bias + col));
            float v0 = acc[mt][nt][0] + bv.x;
            float v1 = acc[mt][nt][1] + bv.y;
            float v2 = acc[mt][nt][2] + bv.x;
            float v3 = acc[mt][nt][3] + bv.y;
            if (RELU) {
                v0 = fmaxf(v0, 0.f); v1 = fmaxf(v1, 0.f);
                v2 = fmaxf(v2, 0.f); v3 = fmaxf(v3, 0.f);
            }
            if (WF32) {
                if (fullvec && col + 2 <= Ntot) {
                    *(float2*)(Cf32 + (size_t)row0 * Ntot + col) = make_float2(v0, v1);
                    *(float2*)(Cf32 + (size_t)row1 * Ntot + col) = make_float2(v2, v3);
                } else {
                    if (col < Ntot) {
                        Cf32[(size_t)row0 * Ntot + col] = v0;
                        Cf32[(size_t)row1 * Ntot + col] = v2;
                    }
                    if (col + 1 < Ntot) {
                        Cf32[(size_t)row0 * Ntot + col + 1] = v1;
                        Cf32[(size_t)row1 * Ntot + col + 1] = v3;
                    }
                }
            }
            if (WH16) {
                *(uint32_t*)(Ch + (size_t)row0 * Ntot + col) = pack_h2(v0, v1);
                *(uint32_t*)(Ch + (size_t)row1 * Ntot + col) = pack_h2(v2, v3);
            }
        }
    }
}

// ---------------- streaming online-softmax attention (R12 WIN, unchanged) ----------------
#define ACH 8
#define ASTAGES 3
#define A_SMEM ((ASTAGES * ACH * H + H + 4 * ACH + 8) * 4)

__global__ __launch_bounds__(256)
void attn_kernel(const float* __restrict__ vf,
                 const float* __restrict__ rel_base,
                 const int* __restrict__ scats,
                 const int* __restrict__ ocats,
                 __half* __restrict__ rf) {
    extern __shared__ float sm[];
    float* ring  = sm;
    float* svf   = ring + ASTAGES * ACH * H;
    float* sdot  = svf + H;
    float* ssq   = sdot + ACH;
    float* sw    = ssq + ACH;
    float* sred  = sw + ACH;
    float* sstat = sred + 8;

    const int n = blockIdx.x;
    const int tid = threadIdx.x;
    const int lane = tid & 31;
    const int warp = tid >> 5;

    const int s = scats[n];
    const int o = ocats[n];
    const float* relp = rel_base + (((size_t)s * RR) * CC + o) * H;

    auto load_chunk = [&](int tc) {
        float* dst = ring + (tc % ASTAGES) * (ACH * H);
#pragma unroll
        for (int i = 0; i < 4; i++) {
            int idx = tid + i * 256;
            int j = idx >> 7;
            int col4 = idx & 127;
            int r = tc * ACH + j;
            if (r < RR)
                cp_async16(smem_u32(dst + j * H + col4 * 4),
                           relp + (size_t)r * CC * H + col4 * 4);
        }
        cp_commit();
    };

    if (tid < 128)
        ((float4*)svf)[tid] = __ldg(&((const float4*)(vf + (size_t)n * H))[tid]);

    load_chunk(0);
    load_chunk(1);
    load_chunk(2);

    __syncthreads();
    {
        float v0 = svf[tid], v1 = svf[tid + 256];
        float part = v0 * v0 + v1 * v1;
#pragma unroll
        for (int off = 16; off > 0; off >>= 1)
            part += __shfl_xor_sync(0xffffffffu, part, off);
        if (lane == 0) sred[warp] = part;
    }

    const int chunks = (RR + ACH - 1) / ACH;
    float acc0 = 0.f, acc1 = 0.f;
    float m_run = -1e30f, s_run = 0.f, vn = 0.f;

    for (int tc = 0; tc < chunks; tc++) {
        CP_WAIT(2);
        __syncthreads();

        {
            const float4* cb4 = (const float4*)(ring + (tc % ASTAGES) * (ACH * H) + warp * H);
            const float4* vf4s = (const float4*)svf;
            float dot = 0.f, sq = 0.f;
#pragma unroll
            for (int i = 0; i < 4; i++) {
                float4 x = cb4[lane + 32 * i];
                float4 v = vf4s[lane + 32 * i];
                dot += x.x * v.x + x.y * v.y + x.z * v.z + x.w * v.w;
                sq  += x.x * x.x + x.y * x.y + x.z * x.z + x.w * x.w;
            }
#pragma unroll
            for (int off = 16; off > 0; off >>= 1) {
                dot += __shfl_down_sync(0xffffffffu, dot, off);
                sq  += __shfl_down_sync(0xffffffffu, sq, off);
            }
            if (lane == 0) { sdot[warp] = dot; ssq[warp] = sq; }
        }
        __syncthreads();

        if (warp == 0) {
            if (tc == 0) {
                float vsq = (lane < 8) ? sred[lane] : 0.f;
#pragma unroll
                for (int off = 4; off > 0; off >>= 1)
                    vsq += __shfl_xor_sync(0xffffffffu, vsq, off);
                vsq = __shfl_sync(0xffffffffu, vsq, 0);
                vn = sqrtf(vsq);
            }
            int r = tc * ACH + lane;
            float c = -1e30f;
            if (lane < ACH && r < RR)
                c = sdot[lane] / fmaxf(vn * sqrtf(ssq[lane]), EPSV);
            float mc = c;
#pragma unroll
            for (int off = 16; off > 0; off >>= 1)
                mc = fmaxf(mc, __shfl_xor_sync(0xffffffffu, mc, off));
            float m_new = fmaxf(m_run, mc);
            float w = (lane < ACH) ? __expf(c - m_new) : 0.f;
            float wsum = w;
#pragma unroll
            for (int off = 16; off > 0; off >>= 1)
                wsum += __shfl_xor_sync(0xffffffffu, wsum, off);
            float scale = __expf(m_run - m_new);
            s_run = s_run * scale + wsum;
            m_run = m_new;
            if (lane < ACH) sw[lane] = w;
            if (lane == 0) sstat[0] = scale;
            if (lane == 0 && tc == chunks - 1) sstat[1] = s_run;
        }
        __syncthreads();

        {
            float scale = sstat[0];
            acc0 *= scale; acc1 *= scale;
            const float* cb = ring + (tc % ASTAGES) * (ACH * H);
#pragma unroll
            for (int r = 0; r < ACH; r++) {
                float wr = sw[r];
                acc0 = fmaf(wr, cb[r * H + tid], acc0);
                acc1 = fmaf(wr, cb[r * H + tid + 256], acc1);
            }
        }
        __syncthreads();

        if (tc + 3 < chunks) load_chunk(tc + 3);
        else cp_commit();
    }

    float inv = 1.f / sstat[1];
    float att0 = acc0 * inv, att1 = acc1 * inv;
    float vv0 = svf[tid], vv1 = svf[tid + 256];

    size_t base = (size_t)n * 2 * H;
    rf[base + tid]           = __float2half_rn(vv0);
    rf[base + tid + 256]     = __float2half_rn(vv1);
    rf[base + H + tid]       = __float2half_rn(att0);
    rf[base + H + tid + 256] = __float2half_rn(att1);
}

// ---------------- launch ----------------
extern "C" void kernel_launch(void* const* d_in, const int* in_sizes, int n_in,
                              void* d_out, int out_size) {
    if (n_in < 14) return;
    const float* sfeat = (const float*)d_in[0];
    const float* pfeat = (const float*)d_in[1];
    const float* ofeat = (const float*)d_in[2];
    const float* rel   = (const float*)d_in[3];
    const float* w1    = (const float*)d_in[4];
    const float* b1    = (const float*)d_in[5];
    const float* w2    = (const float*)d_in[6];
    const float* b2    = (const float*)d_in[7];
    const float* rw1   = (const float*)d_in[8];
    const float* rb1   = (const float*)d_in[9];
    const float* rw2   = (const float*)d_in[10];
    const float* rb2   = (const float*)d_in[11];
    const int*   scats = (const int*)d_in[12];
    const int*   ocats = (const int*)d_in[13];
    float* out = (float*)d_out;

    __half *p_vcat, *p_h, *p_rf, *p_h2, *p_w1t, *p_w2t, *p_rw1t, *p_rw2t;
    float *p_vf;
    void *p_rw2t_v;
    cudaGetSymbolAddress((void**)&p_vcat, g_vcat);
    cudaGetSymbolAddress((void**)&p_h, g_h);
    cudaGetSymbolAddress((void**)&p_vf, g_vf);
    cudaGetSymbolAddress((void**)&p_rf, g_rf);
    cudaGetSymbolAddress((void**)&p_h2, g_h2);
    cudaGetSymbolAddress((void**)&p_w1t, g_w1t);
    cudaGetSymbolAddress((void**)&p_w2t, g_w2t);
    cudaGetSymbolAddress((void**)&p_rw1t, g_rw1t);
    cudaGetSymbolAddress((void**)&p_rw2t, g_rw2t);
    p_rw2t_v = (void*)p_rw2t;
    float* p_rb2p;
    cudaGetSymbolAddress((void**)&p_rb2p, g_rb2p);

    const int thr = 256;

    // 0) weight transpose -> fp16 (+ padded rw2t / bias)
    wtrans_kernel<<<(int)(((size_t)3 * H * H + thr - 1) / thr), thr>>>(w1, p_w1t, 3 * H, H);
    wtrans_kernel<<<(int)(((size_t)H * H + thr - 1) / thr), thr>>>(w2, p_w2t, H, H);
    wtrans_kernel<<<(int)(((size_t)2 * H * H + thr - 1) / thr), thr>>>(rw1, p_rw1t, 2 * H, H);
    cudaMemsetAsync(p_rw2t_v, 0, (size_t)128 * H * sizeof(__half));
    wtrans_kernel<<<(int)(((size_t)H * PP + thr - 1) / thr), thr>>>(rw2, p_rw2t, H, PP);
    biaspad_kernel<<<1, 128>>>(rb2);

    // 1) concat -> fp16
    {
        size_t total4 = (size_t)NROWS * 3 * H / 4;
        concat_kernel<<<(int)((total4 + thr - 1) / thr), thr>>>(sfeat, pfeat, ofeat);
    }
    // 2) h = relu(vcat @ w1 + b1) -> fp16
    {
        cudaFuncSetAttribute(tgemm_kernel<true, false, true>,
                             cudaFuncAttributeMaxDynamicSharedMemorySize, TG_SMEM);
        dim3 grid(H / 128, NROWS / 128);
        tgemm_kernel<true, false, true><<<grid, 256, TG_SMEM>>>(
            p_vcat, p_w1t, b1, p_h, nullptr, 3 * H, H);
    }
    // 3) vf = relu(h @ w2 + b2) -> f32
    {
        cudaFuncSetAttribute(tgemm_kernel<false, true, true>,
                             cudaFuncAttributeMaxDynamicSharedMemorySize, TG_SMEM);
        dim3 grid(H / 128, NROWS / 128);
        tgemm_kernel<false, true, true><<<grid, 256, TG_SMEM>>>(
            p_h, p_w2t, b2, nullptr, p_vf, H, H);
    }
    // 4) streaming attention -> rf fp16
    {
        cudaFuncSetAttribute(attn_kernel, cudaFuncAttributeMaxDynamicSharedMemorySize, A_SMEM);
        attn_kernel<<<NROWS, 256, A_SMEM>>>(p_vf, rel, scats, ocats, p_rf);
    }
    // 5) h2 = relu(rf @ rw1 + rb1) -> fp16
    {
        dim3 grid(H / 128, NROWS / 128);
        tgemm_kernel<true, false, true><<<grid, 256, TG_SMEM>>>(
            p_rf, p_rw1t, rb1, p_h2, nullptr, 2 * H, H);
    }
    // 6) plogits = h2 @ rw2 + rb2  (tensor path, padded N, guarded epilogue)
    {
        cudaFuncSetAttribute(tgemm_kernel<false, true, false>,
                             cudaFuncAttributeMaxDynamicSharedMemorySize, TG_SMEM);
        dim3 grid(1, NROWS / 128);
        tgemm_kernel<false, true, false><<<grid, 256, TG_SMEM>>>(
            p_h2, p_rw2t, p_rb2p, nullptr, out, H, PP);
    }
}

// round 17
// speedup vs baseline: 1.2581x; 1.2492x over previous
#include <cuda_runtime.h>
#include <cuda_fp16.h>
#include <math.h>
#include <stdint.h>
#include <string.h>

#define NROWS 8192
#define H 512
#define CC 100
#define RR 69
#define PP 69
#define EPSV 1e-8f

typedef unsigned long long ull;

// ---------------- scratch (device globals, no runtime alloc) ----------------
__device__ __half g_vcat[(size_t)NROWS * 3 * H];
__device__ __half g_h[(size_t)NROWS * H];
__device__ float  g_vf[(size_t)NROWS * H];
__device__ __half g_rf[(size_t)NROWS * 2 * H];
__device__ float  g_h2[(size_t)NROWS * H];
__device__ __half g_w1t[(size_t)H * 3 * H];
__device__ __half g_w2t[(size_t)H * H];
__device__ __half g_rw1t[(size_t)H * 2 * H];

// ---------------- helpers ----------------
__device__ __forceinline__ uint32_t pack_h2(float a, float b) {
    __half2 h = __floats2half2_rn(a, b);
    uint32_t r; memcpy(&r, &h, 4); return r;
}
__device__ __forceinline__ uint32_t smem_u32(const void* p) {
    return (uint32_t)__cvta_generic_to_shared(p);
}
__device__ __forceinline__ void cp_async16(uint32_t smem_dst, const void* gmem_src) {
    asm volatile("cp.async.cg.shared.global [%0], [%1], 16;" :: "r"(smem_dst), "l"(gmem_src) : "memory");
}
__device__ __forceinline__ void cp_commit() {
    asm volatile("cp.async.commit_group;" ::: "memory");
}
#define CP_WAIT(n) asm volatile("cp.async.wait_group %0;" :: "n"(n) : "memory")

__device__ __forceinline__ void mma16816(float* d, const uint32_t* a, const uint32_t* b) {
    asm volatile(
        "mma.sync.aligned.m16n8k16.row.col.f32.f16.f16.f32 "
        "{%0,%1,%2,%3},{%4,%5,%6,%7},{%8,%9},{%0,%1,%2,%3};"
        : "+f"(d[0]), "+f"(d[1]), "+f"(d[2]), "+f"(d[3])
        : "r"(a[0]), "r"(a[1]), "r"(a[2]), "r"(a[3]), "r"(b[0]), "r"(b[1]));
}
__device__ __forceinline__ void ldsm4(uint32_t& r0, uint32_t& r1, uint32_t& r2, uint32_t& r3,
                                      uint32_t addr) {
    asm volatile("ldmatrix.sync.aligned.m8n8.x4.shared.b16 {%0,%1,%2,%3}, [%4];"
        : "=r"(r0), "=r"(r1), "=r"(r2), "=r"(r3) : "r"(addr));
}

// ---------------- concat -> fp16 ----------------
__global__ void concat_kernel(const float* __restrict__ s,
                              const float* __restrict__ p,
                              const float* __restrict__ o) {
    size_t idx = (size_t)blockIdx.x * blockDim.x + threadIdx.x;   // float4 index
    size_t total = (size_t)NROWS * 3 * H / 4;
    if (idx >= total) return;
    size_t row = idx / (3 * H / 4);
    size_t col4 = idx % (3 * H / 4);
    const float4* src;
    size_t within;
    if (col4 < H / 4)            { src = (const float4*)s; within = col4; }
    else if (col4 < 2 * (H / 4)) { src = (const float4*)p; within = col4 - H / 4; }
    else                         { src = (const float4*)o; within = col4 - 2 * (H / 4); }
    float4 v = src[row * (H / 4) + within];
    uint32_t* d = (uint32_t*)(g_vcat + idx * 4);
    d[0] = pack_h2(v.x, v.y);
    d[1] = pack_h2(v.z, v.w);
}

// ---------------- weight transpose: W[K,N] f32 -> T[N,K] fp16 ----------------
__global__ void wtrans_kernel(const float* __restrict__ W,
                              __half* __restrict__ T,
                              int K, int N) {
    size_t idx = (size_t)blockIdx.x * blockDim.x + threadIdx.x;
    size_t total = (size_t)K * N;
    if (idx >= total) return;
    int n = (int)(idx / K);
    int k = (int)(idx % K);
    T[idx] = __float2half_rn(W[(size_t)k * N + n]);
}

// ---------------- fp16 single-pass mma.sync GEMM, 3-stage cp.async + pipelined ldmatrix ----------------
#define TG_LDS 72
#define TG_STAGES 3
#define TG_STAGE_ELEMS (128 * TG_LDS)
#define TG_SMEM (2 * TG_STAGES * TG_STAGE_ELEMS * 2)   // 110592 B
#define TG_ROWB (TG_LDS * 2)                           // 144 B row stride

template<bool WH16, bool WF32, bool RELU>
__global__ __launch_bounds__(256, 2)
void tgemm_kernel(const __half* __restrict__ A, const __half* __restrict__ B,
                  const float* __restrict__ bias,
                  __half* __restrict__ Ch, float* __restrict__ Cf32,
                  int K, int Ntot) {
    extern __shared__ __align__(16) __half smem[];

    const int tid = threadIdx.x;
    const int wid = tid >> 5;
    const int lane = tid & 31;
    const int g = lane >> 2;
    const int t = lane & 3;
    const int wm = wid & 3;
    const int wn = wid >> 2;
    const int bm = blockIdx.y * 128;
    const int bn = blockIdx.x * 128;

    const int C = K >> 6;          // single pass: chunks of 64

    const uint32_t aoff = (uint32_t)((wm * 32 + (lane & 15)) * TG_ROWB + ((lane >> 4) * 8) * 2);
    const uint32_t boff = (uint32_t)((wn * 64 + ((lane >> 3) >> 1) * 8 + (lane & 7)) * TG_ROWB
                                     + (((lane >> 3) & 1) * 8) * 2);

    float acc[2][8][4];
#pragma unroll
    for (int i = 0; i < 2; i++)
#pragma unroll
        for (int j = 0; j < 8; j++)
#pragma unroll
            for (int q = 0; q < 4; q++) acc[i][j][q] = 0.f;

    auto load_chunk = [&](int c, int s) {
        int kc = c << 6;
        uint32_t abase = smem_u32(smem + s * TG_STAGE_ELEMS);
        uint32_t bbase = smem_u32(smem + (TG_STAGES + s) * TG_STAGE_ELEMS);
#pragma unroll
        for (int i = 0; i < 4; i++) {
            int seg = tid + i * 256;
            int row = seg >> 3, sg = seg & 7;
            cp_async16(abase + (row * TG_LDS + sg * 8) * 2,
                       A + (size_t)(bm + row) * K + kc + sg * 8);
        }
#pragma unroll
        for (int i = 0; i < 4; i++) {
            int seg = tid + i * 256;
            int row = seg >> 3, sg = seg & 7;
            cp_async16(bbase + (row * TG_LDS + sg * 8) * 2,
                       B + (size_t)(bn + row) * K + kc + sg * 8);
        }
        cp_commit();
    };

    load_chunk(0, 0);
    load_chunk(1, 1);
    load_chunk(2, 2);

    for (int c = 0; c < C; c++) {
        const int s = c % TG_STAGES;
        CP_WAIT(2);
        __syncthreads();

        const uint32_t abase = smem_u32(smem + s * TG_STAGE_ELEMS) + aoff;
        const uint32_t bbase = smem_u32(smem + (TG_STAGES + s) * TG_STAGE_ELEMS) + boff;

        uint32_t af[2][2][4];
        uint32_t bf[2][4][4];

        ldsm4(af[0][0][0], af[0][0][1], af[0][0][2], af[0][0][3], abase);
        ldsm4(af[0][1][0], af[0][1][1], af[0][1][2], af[0][1][3], abase + 16 * TG_ROWB);
#pragma unroll
        for (int ntp = 0; ntp < 4; ntp++)
            ldsm4(bf[0][ntp][0], bf[0][ntp][1], bf[0][ntp][2], bf[0][ntp][3],
                  bbase + ntp * 16 * TG_ROWB);

#pragma unroll
        for (int ks = 0; ks < 4; ks++) {
            const int cur = ks & 1;
            const int nxt = cur ^ 1;
            if (ks < 3) {
                const uint32_t k2 = (ks + 1) * 32;
                ldsm4(af[nxt][0][0], af[nxt][0][1], af[nxt][0][2], af[nxt][0][3], abase + k2);
                ldsm4(af[nxt][1][0], af[nxt][1][1], af[nxt][1][2], af[nxt][1][3],
                      abase + 16 * TG_ROWB + k2);
#pragma unroll
                for (int ntp = 0; ntp < 4; ntp++)
                    ldsm4(bf[nxt][ntp][0], bf[nxt][ntp][1], bf[nxt][ntp][2], bf[nxt][ntp][3],
                          bbase + ntp * 16 * TG_ROWB + k2);
            }
#pragma unroll
            for (int ntp = 0; ntp < 4; ntp++) {
                mma16816(acc[0][2 * ntp],     af[cur][0], bf[cur][ntp]);
                mma16816(acc[1][2 * ntp],     af[cur][1], bf[cur][ntp]);
                mma16816(acc[0][2 * ntp + 1], af[cur][0], bf[cur][ntp] + 2);
                mma16816(acc[1][2 * ntp + 1], af[cur][1], bf[cur][ntp] + 2);
            }
        }
        __syncthreads();
        if (c + 3 < C) load_chunk(c + 3, s);
        else cp_commit();
    }

    // epilogue
#pragma unroll
    for (int mt = 0; mt < 2; mt++) {
        int row0 = bm + wm * 32 + mt * 16 + g;
        int row1 = row0 + 8;
#pragma unroll
        for (int nt = 0; nt < 8; nt++) {
            int col = bn + wn * 64 + nt * 8 + 2 * t;
            float2 bv = __ldg((const float2*)(bias + col));
            float v0 = acc[mt][nt][0] + bv.x;
            float v1 = acc[mt][nt][1] + bv.y;
            float v2 = acc[mt][nt][2] + bv.x;
            float v3 = acc[mt][nt][3] + bv.y;
            if (RELU) {
                v0 = fmaxf(v0, 0.f); v1 = fmaxf(v1, 0.f);
                v2 = fmaxf(v2, 0.f); v3 = fmaxf(v3, 0.f);
            }
            if (WF32) {
                *(float2*)(Cf32 + (size_t)row0 * Ntot + col) = make_float2(v0, v1);
                *(float2*)(Cf32 + (size_t)row1 * Ntot + col) = make_float2(v2, v3);
            }
            if (WH16) {
                *(uint32_t*)(Ch + (size_t)row0 * Ntot + col) = pack_h2(v0, v1);
                *(uint32_t*)(Ch + (size_t)row1 * Ntot + col) = pack_h2(v2, v3);
            }
        }
    }
}

// ---------------- FFMA2 SGEMM (final N=69 GEMM, fp32) ----------------
__device__ __forceinline__ ull pack2(float lo, float hi) {
    ull r; asm("mov.b64 %0, {%1, %2};" : "=l"(r) : "f"(lo), "f"(hi)); return r;
}
__device__ __forceinline__ void unpack2(ull v, float& lo, float& hi) {
    asm("mov.b64 {%0, %1}, %2;" : "=f"(lo), "=f"(hi) : "l"(v));
}
__device__ __forceinline__ void fma2(ull& d, ull a, ull b) {
    asm("fma.rn.f32x2 %0, %1, %2, %3;" : "=l"(d) : "l"(a), "l"(b), "l"(d));
}

template<bool RELU>
__global__ __launch_bounds__(256)
void sgemm_kernel(const float* __restrict__ A, const float* __restrict__ B,
                  const float* __restrict__ bias, float* __restrict__ C,
                  int M, int Kd, int Nd) {
    __shared__ float As[8][132];
    __shared__ float Bs[8][128];

    const int bm = blockIdx.y * 128;
    const int bn = blockIdx.x * 128;
    const int tid = threadIdx.x;
    const int arow = tid >> 1;
    const int acol = (tid & 1) * 4;
    const int brow = tid >> 5;
    const int bcol = (tid & 31) * 4;
    const int tx = tid & 15;
    const int ty = tid >> 4;

    ull acc2[4][8];
#pragma unroll
    for (int i = 0; i < 4; i++)
#pragma unroll
        for (int j = 0; j < 8; j++) acc2[i][j] = 0ull;

    const bool full_n = (bn + 128 <= Nd);

    for (int k0 = 0; k0 < Kd; k0 += 8) {
        float4 a4 = *(const float4*)(A + (size_t)(bm + arow) * Kd + k0 + acol);
        As[acol + 0][arow] = a4.x;
        As[acol + 1][arow] = a4.y;
        As[acol + 2][arow] = a4.z;
        As[acol + 3][arow] = a4.w;
        if (full_n) {
            *(float4*)&Bs[brow][bcol] =
                *(const float4*)(B + (size_t)(k0 + brow) * Nd + bn + bcol);
        } else {
#pragma unroll
            for (int c = 0; c < 4; c++) {
                int col = bn + bcol + c;
                Bs[brow][bcol + c] = (col < Nd) ? B[(size_t)(k0 + brow) * Nd + col] : 0.f;
            }
        }
        __syncthreads();
#pragma unroll
        for (int k = 0; k < 8; k++) {
            ulonglong2 av0 = *(const ulonglong2*)&As[k][ty * 8];
            ulonglong2 av1 = *(const ulonglong2*)&As[k][ty * 8 + 4];
            ull a2[4] = {av0.x, av0.y, av1.x, av1.y};
            float4 blo = *(const float4*)&Bs[k][tx * 8];
            float4 bhi = *(const float4*)&Bs[k][tx * 8 + 4];
            ull b2[8];
            b2[0] = pack2(blo.x, blo.x); b2[1] = pack2(blo.y, blo.y);
            b2[2] = pack2(blo.z, blo.z); b2[3] = pack2(blo.w, blo.w);
            b2[4] = pack2(bhi.x, bhi.x); b2[5] = pack2(bhi.y, bhi.y);
            b2[6] = pack2(bhi.z, bhi.z); b2[7] = pack2(bhi.w, bhi.w);
#pragma unroll
            for (int i = 0; i < 4; i++)
#pragma unroll
                for (int j = 0; j < 8; j++)
                    fma2(acc2[i][j], a2[i], b2[j]);
        }
        __syncthreads();
    }
#pragma unroll
    for (int i = 0; i < 4; i++) {
        int row_lo = bm + ty * 8 + 2 * i;
        float* c0 = C + (size_t)row_lo * Nd;
        float* c1 = C + (size_t)(row_lo + 1) * Nd;
#pragma unroll
        for (int j = 0; j < 8; j++) {
            int col = bn + tx * 8 + j;
            if (col < Nd) {
                float lo, hi;
                unpack2(acc2[i][j], lo, hi);
                float bv = bias[col];
                lo += bv; hi += bv;
                if (RELU) { lo = fmaxf(lo, 0.f); hi = fmaxf(hi, 0.f); }
                c0[col] = lo;
                c1[col] = hi;
            }
        }
    }
}

// ---------------- streaming online-softmax attention (writes rf fp16) ----------------
#define ACH 8
#define ASTAGES 3
#define A_SMEM ((ASTAGES * ACH * H + H + 4 * ACH + 8) * 4)

__global__ __launch_bounds__(256)
void attn_kernel(const float* __restrict__ vf,
                 const float* __restrict__ rel_base,
                 const int* __restrict__ scats,
                 const int* __restrict__ ocats,
                 __half* __restrict__ rf) {
    extern __shared__ float sm[];
    float* ring  = sm;
    float* svf   = ring + ASTAGES * ACH * H;
    float* sdot  = svf + H;
    float* ssq   = sdot + ACH;
    float* sw    = ssq + ACH;
    float* sred  = sw + ACH;
    float* sstat = sred + 8;

    const int n = blockIdx.x;
    const int tid = threadIdx.x;
    const int lane = tid & 31;
    const int warp = tid >> 5;

    const int s = scats[n];
    const int o = ocats[n];
    const float* relp = rel_base + (((size_t)s * RR) * CC + o) * H;

    auto load_chunk = [&](int tc) {
        float* dst = ring + (tc % ASTAGES) * (ACH * H);
#pragma unroll
        for (int i = 0; i < 4; i++) {
            int idx = tid + i * 256;
            int j = idx >> 7;
            int col4 = idx & 127;
            int r = tc * ACH + j;
            if (r < RR)
                cp_async16(smem_u32(dst + j * H + col4 * 4),
                           relp + (size_t)r * CC * H + col4 * 4);
        }
        cp_commit();
    };

    if (tid < 128)
        ((float4*)svf)[tid] = __ldg(&((const float4*)(vf + (size_t)n * H))[tid]);

    load_chunk(0);
    load_chunk(1);
    load_chunk(2);

    __syncthreads();
    {
        float v0 = svf[tid], v1 = svf[tid + 256];
        float part = v0 * v0 + v1 * v1;
#pragma unroll
        for (int off = 16; off > 0; off >>= 1)
            part += __shfl_xor_sync(0xffffffffu, part, off);
        if (lane == 0) sred[warp] = part;
    }

    const int chunks = (RR + ACH - 1) / ACH;
    float acc0 = 0.f, acc1 = 0.f;
    float m_run = -1e30f, s_run = 0.f, vn = 0.f;

    for (int tc = 0; tc < chunks; tc++) {
        CP_WAIT(2);
        __syncthreads();

        {
            const float4* cb4 = (const float4*)(ring + (tc % ASTAGES) * (ACH * H) + warp * H);
            const float4* vf4s = (const float4*)svf;
            float dot = 0.f, sq = 0.f;
#pragma unroll
            for (int i = 0; i < 4; i++) {
                float4 x = cb4[lane + 32 * i];
                float4 v = vf4s[lane + 32 * i];
                dot += x.x * v.x + x.y * v.y + x.z * v.z + x.w * v.w;
                sq  += x.x * x.x + x.y * x.y + x.z * x.z + x.w * x.w;
            }
#pragma unroll
            for (int off = 16; off > 0; off >>= 1) {
                dot += __shfl_down_sync(0xffffffffu, dot, off);
                sq  += __shfl_down_sync(0xffffffffu, sq, off);
            }
            if (lane == 0) { sdot[warp] = dot; ssq[warp] = sq; }
        }
        __syncthreads();

        if (warp == 0) {
            if (tc == 0) {
                float vsq = (lane < 8) ? sred[lane] : 0.f;
#pragma unroll
                for (int off = 4; off > 0; off >>= 1)
                    vsq += __shfl_xor_sync(0xffffffffu, vsq, off);
                vsq = __shfl_sync(0xffffffffu, vsq, 0);
                vn = sqrtf(vsq);
            }
            int r = tc * ACH + lane;
            float c = -1e30f;
            if (lane < ACH && r < RR)
                c = sdot[lane] / fmaxf(vn * sqrtf(ssq[lane]), EPSV);
            float mc = c;
#pragma unroll
            for (int off = 16; off > 0; off >>= 1)
                mc = fmaxf(mc, __shfl_xor_sync(0xffffffffu, mc, off));
            float m_new = fmaxf(m_run, mc);
            float w = (lane < ACH) ? __expf(c - m_new) : 0.f;
            float wsum = w;
#pragma unroll
            for (int off = 16; off > 0; off >>= 1)
                wsum += __shfl_xor_sync(0xffffffffu, wsum, off);
            float scale = __expf(m_run - m_new);
            s_run = s_run * scale + wsum;
            m_run = m_new;
            if (lane < ACH) sw[lane] = w;
            if (lane == 0) sstat[0] = scale;
            if (lane == 0 && tc == chunks - 1) sstat[1] = s_run;
        }
        __syncthreads();

        {
            float scale = sstat[0];
            acc0 *= scale; acc1 *= scale;
            const float* cb = ring + (tc % ASTAGES) * (ACH * H);
#pragma unroll
            for (int r = 0; r < ACH; r++) {
                float wr = sw[r];
                acc0 = fmaf(wr, cb[r * H + tid], acc0);
                acc1 = fmaf(wr, cb[r * H + tid + 256], acc1);
            }
        }
        __syncthreads();

        if (tc + 3 < chunks) load_chunk(tc + 3);
        else cp_commit();
    }

    float inv = 1.f / sstat[1];
    float att0 = acc0 * inv, att1 = acc1 * inv;
    float vv0 = svf[tid], vv1 = svf[tid + 256];

    size_t base = (size_t)n * 2 * H;
    rf[base + tid]           = __float2half_rn(vv0);
    rf[base + tid + 256]     = __float2half_rn(vv1);
    rf[base + H + tid]       = __float2half_rn(att0);
    rf[base + H + tid + 256] = __float2half_rn(att1);
}

// ---------------- launch ----------------
extern "C" void kernel_launch(void* const* d_in, const int* in_sizes, int n_in,
                              void* d_out, int out_size) {
    if (n_in < 14) return;
    const float* sfeat = (const float*)d_in[0];
    const float* pfeat = (const float*)d_in[1];
    const float* ofeat = (const float*)d_in[2];
    const float* rel   = (const float*)d_in[3];
    const float* w1    = (const float*)d_in[4];
    const float* b1    = (const float*)d_in[5];
    const float* w2    = (const float*)d_in[6];
    const float* b2    = (const float*)d_in[7];
    const float* rw1   = (const float*)d_in[8];
    const float* rb1   = (const float*)d_in[9];
    const float* rw2   = (const float*)d_in[10];
    const float* rb2   = (const float*)d_in[11];
    const int*   scats = (const int*)d_in[12];
    const int*   ocats = (const int*)d_in[13];
    float* out = (float*)d_out;

    __half *p_vcat, *p_h, *p_rf, *p_w1t, *p_w2t, *p_rw1t;
    float *p_vf, *p_h2;
    cudaGetSymbolAddress((void**)&p_vcat, g_vcat);
    cudaGetSymbolAddress((void**)&p_h, g_h);
    cudaGetSymbolAddress((void**)&p_vf, g_vf);
    cudaGetSymbolAddress((void**)&p_rf, g_rf);
    cudaGetSymbolAddress((void**)&p_h2, g_h2);
    cudaGetSymbolAddress((void**)&p_w1t, g_w1t);
    cudaGetSymbolAddress((void**)&p_w2t, g_w2t);
    cudaGetSymbolAddress((void**)&p_rw1t, g_rw1t);

    const int thr = 256;

    // 0) weight transpose -> fp16
    wtrans_kernel<<<(int)(((size_t)3 * H * H + thr - 1) / thr), thr>>>(w1, p_w1t, 3 * H, H);
    wtrans_kernel<<<(int)(((size_t)H * H + thr - 1) / thr), thr>>>(w2, p_w2t, H, H);
    wtrans_kernel<<<(int)(((size_t)2 * H * H + thr - 1) / thr), thr>>>(rw1, p_rw1t, 2 * H, H);

    // 1) concat -> fp16
    {
        size_t total4 = (size_t)NROWS * 3 * H / 4;
        concat_kernel<<<(int)((total4 + thr - 1) / thr), thr>>>(sfeat, pfeat, ofeat);
    }
    // 2) h = relu(vcat @ w1 + b1) -> fp16
    {
        cudaFuncSetAttribute(tgemm_kernel<true, false, true>,
                             cudaFuncAttributeMaxDynamicSharedMemorySize, TG_SMEM);
        dim3 grid(H / 128, NROWS / 128);
        tgemm_kernel<true, false, true><<<grid, 256, TG_SMEM>>>(
            p_vcat, p_w1t, b1, p_h, nullptr, 3 * H, H);
    }
    // 3) vf = relu(h @ w2 + b2) -> f32
    {
        cudaFuncSetAttribute(tgemm_kernel<false, true, true>,
                             cudaFuncAttributeMaxDynamicSharedMemorySize, TG_SMEM);
        dim3 grid(H / 128, NROWS / 128);
        tgemm_kernel<false, true, true><<<grid, 256, TG_SMEM>>>(
            p_h, p_w2t, b2, nullptr, p_vf, H, H);
    }
    // 4) streaming attention -> rf fp16
    {
        cudaFuncSetAttribute(attn_kernel, cudaFuncAttributeMaxDynamicSharedMemorySize, A_SMEM);
        attn_kernel<<<NROWS, 256, A_SMEM>>>(p_vf, rel, scats, ocats, p_rf);
    }
    // 5) h2 = relu(rf @ rw1 + rb1) -> f32
    {
        dim3 grid(H / 128, NROWS / 128);
        tgemm_kernel<false, true, true><<<grid, 256, TG_SMEM>>>(
            p_rf, p_rw1t, rb1, nullptr, p_h2, 2 * H, H);
    }
    // 6) plogits = h2 @ rw2 + rb2   (FFMA2 fp32, Nd=69)
    {
        dim3 grid(1, NROWS / 128);
        sgemm_kernel<false><<<grid, 256>>>(p_h2, rw2, rb2, out, NROWS, H, PP);
    }
}